// round 4
// baseline (speedup 1.0000x reference)
#include <cuda_runtime.h>

#define BATCH 16
#define CIN   512
#define MID   128
#define GRP   4
#define H     56
#define W     56
#define HW    (H*W)
#define MH    7
#define MW    7
#define EPSV  1e-5f

// Scratch: post-mask intermediate activations (device globals, no alloc).
__device__ float g_y1[BATCH * MID * HW];   // relu(bn1(conv1(x*m))) * m
__device__ float g_y2[BATCH * MID * HW];   // relu(bn2(conv2(y1))) * m

// ---------------------------------------------------------------------------
// Kernel 1: 1x1 grouped conv (512->128) + BN + ReLU, 8x8 tile, ONE group/CTA.
// 128 thr: pxq = t>>3 (16 quads of 4 px), ocq = t&7 (8 slices of 4 oc).
// Per ic: LDS.128(x, 4-addr bcast) + LDS.128(w) + 16 FFMA.
// K=128 split into 8 chunks of 16 ic, ping-pong double buffer, reg prefetch.
// Mask is per-CTA all-or-nothing -> no idle warps.
// ---------------------------------------------------------------------------
__global__ __launch_bounds__(128) void k1_conv1(
    const float* __restrict__ x, const float* __restrict__ mask,
    const float* __restrict__ w1,
    const float* __restrict__ g1, const float* __restrict__ b1,
    const float* __restrict__ m1, const float* __restrict__ v1)
{
    const int bh = blockIdx.x / 7, bw = blockIdx.x % 7;
    const int g = blockIdx.y, b = blockIdx.z;
    const int h0 = bh * 8, w0 = bw * 8;
    const int t = threadIdx.x;
    const int pxq = t >> 3, ocq = t & 7;
    const int r = pxq >> 1, cst = (pxq & 1) * 4;

    const float m = mask[((b * GRP + g) * MH + bh) * MW + bw];

    if (m == 0.0f) {
        const float4 z = make_float4(0.f, 0.f, 0.f, 0.f);
        #pragma unroll
        for (int k = 0; k < 4; k++) {
            int gc = g * 32 + ocq * 4 + k;
            *(float4*)&g_y1[((b * MID + gc) * H + h0 + r) * W + w0 + cst] = z;
        }
        return;
    }

    __shared__ float  w_s[128][36];     // [ic][oc], pad 36 (144B rows, 16B-aligned)
    __shared__ float4 x_s[2][16][16];   // [buf][icc][pxq]  8KB

    // weights: w1[(g*32+oc)*128 + ic] -> w_s[ic][oc]
    const float* w1g = w1 + (g * 32) * 128;
    #pragma unroll
    for (int i = t; i < 32 * 128; i += 128)
        w_s[i & 127][i >> 7] = w1g[i];

    // loader coords: 2 float4 per thread per chunk (ids t and t+128)
    const int ic0 = t >> 4, p40 = t & 15;
    const int rr0 = p40 >> 1, cc0 = (p40 & 1) * 4;
    const float* xb = x + ((long)(b * CIN + g * 128) * H) * W;
    const float* xp0 = xb + ((long)(ic0    ) * H + h0 + rr0) * W + w0 + cc0;
    const float* xp1 = xb + ((long)(ic0 + 8) * H + h0 + rr0) * W + w0 + cc0;

    float4 n0 = *(const float4*)xp0;
    float4 n1 = *(const float4*)xp1;
    x_s[0][ic0][p40] = n0;
    x_s[0][ic0 + 8][p40] = n1;
    __syncthreads();

    float acc[4][4];
    #pragma unroll
    for (int k = 0; k < 4; k++)
        #pragma unroll
        for (int q = 0; q < 4; q++) acc[k][q] = 0.0f;

    for (int cc = 0; cc < 8; cc++) {          // 8 chunks of 16 ic
        if (cc < 7) {
            n0 = *(const float4*)(xp0 + (long)(cc + 1) * 16 * HW);
            n1 = *(const float4*)(xp1 + (long)(cc + 1) * 16 * HW);
        }
        const int buf = cc & 1;
        #pragma unroll
        for (int icc = 0; icc < 16; icc++) {
            float4 xv = x_s[buf][icc][pxq];
            float4 wv = *(const float4*)&w_s[cc * 16 + icc][ocq * 4];
            acc[0][0] += wv.x * xv.x; acc[0][1] += wv.x * xv.y;
            acc[0][2] += wv.x * xv.z; acc[0][3] += wv.x * xv.w;
            acc[1][0] += wv.y * xv.x; acc[1][1] += wv.y * xv.y;
            acc[1][2] += wv.y * xv.z; acc[1][3] += wv.y * xv.w;
            acc[2][0] += wv.z * xv.x; acc[2][1] += wv.z * xv.y;
            acc[2][2] += wv.z * xv.z; acc[2][3] += wv.z * xv.w;
            acc[3][0] += wv.w * xv.x; acc[3][1] += wv.w * xv.y;
            acc[3][2] += wv.w * xv.z; acc[3][3] += wv.w * xv.w;
        }
        if (cc < 7) {
            x_s[buf ^ 1][ic0][p40] = n0;
            x_s[buf ^ 1][ic0 + 8][p40] = n1;
            __syncthreads();
        }
    }

    #pragma unroll
    for (int k = 0; k < 4; k++) {
        int gc = g * 32 + ocq * 4 + k;
        float sc = g1[gc] * rsqrtf(v1[gc] + EPSV);
        float bi = b1[gc] - m1[gc] * sc;
        float4 v;
        v.x = fmaxf(acc[k][0] * sc + bi, 0.0f);
        v.y = fmaxf(acc[k][1] * sc + bi, 0.0f);
        v.z = fmaxf(acc[k][2] * sc + bi, 0.0f);
        v.w = fmaxf(acc[k][3] * sc + bi, 0.0f);
        *(float4*)&g_y1[((b * MID + gc) * H + h0 + r) * W + w0 + cst] = v;
    }
}

// ---------------------------------------------------------------------------
// Kernel 2: 3x3 grouped conv (128->128, pad 1) + BN + ReLU + mask.
// 256 thr, thread = 2px x 4oc (pxq = t>>3 in [0,32), ocq = t&7).
// Single smem phase (halo + weight slab in dynamic smem), one sync.
// Per ic: 12 scalar LDS + 9 LDS.128 + 72 FFMA.
// ---------------------------------------------------------------------------
#define K2_HALO   3200                     // 32 * 100 floats
#define K2_WSLAB  (32 * 9 * 36)            // [ic][tap][oc pad36]
#define K2_SMEM   ((K2_HALO + K2_WSLAB) * 4)

__global__ __launch_bounds__(256) void k2_conv2(
    const float* __restrict__ mask,
    const float* __restrict__ w2,
    const float* __restrict__ g2, const float* __restrict__ b2,
    const float* __restrict__ m2, const float* __restrict__ v2)
{
    const int bh = blockIdx.x / 7, bw = blockIdx.x % 7;
    const int g = blockIdx.y, b = blockIdx.z;
    const int h0 = bh * 8, w0 = bw * 8;
    const int t = threadIdx.x;
    const int pxq = t >> 3;                // [0,32): 2 px each
    const int ocq = t & 7;                 // [0,8): 4-oc slice
    const int r = pxq >> 2, c0 = (pxq & 3) * 2;

    const float m = mask[((b * GRP + g) * MH + bh) * MW + bw];

    if (m == 0.0f) {
        const float2 z = make_float2(0.f, 0.f);
        #pragma unroll
        for (int k = 0; k < 4; k++) {
            int gc = g * 32 + ocq * 4 + k;
            *(float2*)&g_y2[((b * MID + gc) * H + h0 + r) * W + w0 + c0] = z;
        }
        return;
    }

    extern __shared__ float sm[];
    float* in_s = sm;                      // [32][100]
    float* w_s  = sm + K2_HALO;            // [ic][tap][oc]: ic*324 + tap*36 + oc

    // halo (y1 already post-mask; zero-pad borders)
    for (int i = t; i < 32 * 100; i += 256) {
        int ic = i / 100, p = i % 100;
        int rr = h0 + p / 10 - 1, c2 = w0 + p % 10 - 1;
        float v = 0.0f;
        if (rr >= 0 && rr < H && c2 >= 0 && c2 < W)
            v = g_y1[((b * MID + g * 32 + ic) * H + rr) * W + c2];
        in_s[ic * 100 + p] = v;
    }
    // weights: w2[(g*32+oc)*288 + ic*9 + kk] -> w_s[ic][kk][oc]
    const float* w2g = w2 + (g * 32) * 288;
    for (int i = t; i < 32 * 288; i += 256) {
        int oc = i / 288, rem = i % 288;
        int ic = rem / 9, kk = rem % 9;
        w_s[ic * 324 + kk * 36 + oc] = w2g[i];
    }
    __syncthreads();

    float acc[4][2];
    #pragma unroll
    for (int k = 0; k < 4; k++) { acc[k][0] = 0.0f; acc[k][1] = 0.0f; }

    #pragma unroll 4
    for (int ic = 0; ic < 32; ic++) {
        float xr[3][4];
        #pragma unroll
        for (int kr = 0; kr < 3; kr++)
            #pragma unroll
            for (int j = 0; j < 4; j++)
                xr[kr][j] = in_s[ic * 100 + (r + kr) * 10 + c0 + j];
        #pragma unroll
        for (int kr = 0; kr < 3; kr++) {
            #pragma unroll
            for (int kc = 0; kc < 3; kc++) {
                float4 wv = *(const float4*)&w_s[ic * 324 + (kr * 3 + kc) * 36 + ocq * 4];
                #pragma unroll
                for (int q = 0; q < 2; q++) {
                    float xv = xr[kr][q + kc];
                    acc[0][q] += wv.x * xv;
                    acc[1][q] += wv.y * xv;
                    acc[2][q] += wv.z * xv;
                    acc[3][q] += wv.w * xv;
                }
            }
        }
    }

    #pragma unroll
    for (int k = 0; k < 4; k++) {
        int gc = g * 32 + ocq * 4 + k;
        float sc = g2[gc] * rsqrtf(v2[gc] + EPSV);
        float bi = b2[gc] - m2[gc] * sc;
        float2 v;
        v.x = fmaxf(acc[k][0] * sc + bi, 0.0f);
        v.y = fmaxf(acc[k][1] * sc + bi, 0.0f);
        *(float2*)&g_y2[((b * MID + gc) * H + h0 + r) * W + w0 + c0] = v;
    }
}

// ---------------------------------------------------------------------------
// Kernel 3: 1x1 grouped conv (128->512) + BN + residual + ReLU.
// Thread: 4 px x 8 oc. Per ic: LDS.128(x) + 2x LDS.128(w) + 32 FFMA.
// mask==0 -> out = relu(bias3 + x).
// ---------------------------------------------------------------------------
__global__ __launch_bounds__(256) void k3_conv3(
    const float* __restrict__ x, const float* __restrict__ mask,
    const float* __restrict__ w3,
    const float* __restrict__ g3, const float* __restrict__ b3,
    const float* __restrict__ m3, const float* __restrict__ v3,
    float* __restrict__ out)
{
    const int bh = blockIdx.x / 7, bw = blockIdx.x % 7;
    const int g = blockIdx.y, b = blockIdx.z;
    const int h0 = bh * 8, w0 = bw * 8;
    const int t = threadIdx.x;
    const int pxq = t >> 4, ocp = t & 15;
    const int r = pxq >> 1, cst = (pxq & 1) * 4;

    const float m = mask[((b * GRP + g) * MH + bh) * MW + bw];

    if (m == 0.0f) {
        #pragma unroll
        for (int k = 0; k < 8; k++) {
            int gc = g * 128 + ocp * 8 + k;
            float sc = g3[gc] * rsqrtf(v3[gc] + EPSV);
            float bi = b3[gc] - m3[gc] * sc;
            long idx = ((long)(b * CIN + gc) * H + h0 + r) * W + w0 + cst;
            float4 xv = *(const float4*)&x[idx];
            float4 v;
            v.x = fmaxf(bi + xv.x, 0.0f);
            v.y = fmaxf(bi + xv.y, 0.0f);
            v.z = fmaxf(bi + xv.z, 0.0f);
            v.w = fmaxf(bi + xv.w, 0.0f);
            *(float4*)&out[idx] = v;
        }
        return;
    }

    __shared__ float  w_s[32][132];     // [ic][oc], padded
    __shared__ float4 y_s[32][16];      // [ic][pxq]

    const float* w3g = w3 + (g * 128) * 32;     // [oc=128][ic=32]
    #pragma unroll
    for (int i = t; i < 128 * 32; i += 256)
        w_s[i & 31][i >> 5] = w3g[i];
    #pragma unroll
    for (int j = 0; j < 2; j++) {
        int i = t + j * 256;
        int ic = i >> 4, p4 = i & 15;
        int rr = p4 >> 1, c2 = (p4 & 1) * 4;
        y_s[ic][p4] = *(const float4*)&g_y2[
            ((b * MID + g * 32 + ic) * H + h0 + rr) * W + w0 + c2];
    }
    __syncthreads();

    float acc[8][4];
    #pragma unroll
    for (int k = 0; k < 8; k++)
        #pragma unroll
        for (int q = 0; q < 4; q++) acc[k][q] = 0.0f;

    #pragma unroll 4
    for (int ic = 0; ic < 32; ic++) {
        float4 xv = y_s[ic][pxq];
        const float* wr = &w_s[ic][ocp * 8];
        float4 wa = *(const float4*)wr;
        float4 wb = *(const float4*)(wr + 4);
        float wk[8] = {wa.x, wa.y, wa.z, wa.w, wb.x, wb.y, wb.z, wb.w};
        #pragma unroll
        for (int k = 0; k < 8; k++) {
            acc[k][0] += wk[k] * xv.x;
            acc[k][1] += wk[k] * xv.y;
            acc[k][2] += wk[k] * xv.z;
            acc[k][3] += wk[k] * xv.w;
        }
    }

    #pragma unroll
    for (int k = 0; k < 8; k++) {
        int gc = g * 128 + ocp * 8 + k;
        float sc = g3[gc] * rsqrtf(v3[gc] + EPSV);
        float bi = b3[gc] - m3[gc] * sc;
        long idx = ((long)(b * CIN + gc) * H + h0 + r) * W + w0 + cst;
        float4 xv = *(const float4*)&x[idx];
        float4 v;
        v.x = fmaxf(acc[k][0] * sc + bi + xv.x, 0.0f);
        v.y = fmaxf(acc[k][1] * sc + bi + xv.y, 0.0f);
        v.z = fmaxf(acc[k][2] * sc + bi + xv.z, 0.0f);
        v.w = fmaxf(acc[k][3] * sc + bi + xv.w, 0.0f);
        *(float4*)&out[idx] = v;
    }
}

// ---------------------------------------------------------------------------
extern "C" void kernel_launch(void* const* d_in, const int* in_sizes, int n_in,
                              void* d_out, int out_size)
{
    const float* x    = (const float*)d_in[0];
    const float* mask = (const float*)d_in[1];
    const float* w1   = (const float*)d_in[2];
    const float* g1   = (const float*)d_in[3];
    const float* b1   = (const float*)d_in[4];
    const float* m1   = (const float*)d_in[5];
    const float* v1   = (const float*)d_in[6];
    const float* w2   = (const float*)d_in[7];
    const float* g2   = (const float*)d_in[8];
    const float* b2   = (const float*)d_in[9];
    const float* m2   = (const float*)d_in[10];
    const float* v2   = (const float*)d_in[11];
    const float* w3   = (const float*)d_in[12];
    const float* g3   = (const float*)d_in[13];
    const float* b3   = (const float*)d_in[14];
    const float* m3   = (const float*)d_in[15];
    const float* v3   = (const float*)d_in[16];
    float* out = (float*)d_out;

    cudaFuncSetAttribute(k2_conv2, cudaFuncAttributeMaxDynamicSharedMemorySize, K2_SMEM);

    dim3 grid(49, GRP, BATCH);
    k1_conv1<<<grid, 128>>>(x, mask, w1, g1, b1, m1, v1);
    k2_conv2<<<grid, 256, K2_SMEM>>>(mask, w2, g2, b2, m2, v2);
    k3_conv3<<<grid, 256>>>(x, mask, w3, g3, b3, m3, v3, out);
}

// round 5
// speedup vs baseline: 1.0927x; 1.0927x over previous
#include <cuda_runtime.h>

#define BATCH 16
#define CIN   512
#define MID   128
#define GRP   4
#define H     56
#define W     56
#define HW    (H*W)
#define MH    7
#define MW    7
#define EPSV  1e-5f

// Scratch: post-mask intermediate activations (device globals, no alloc).
__device__ float g_y1[BATCH * MID * HW];   // relu(bn1(conv1(x*m))) * m
__device__ float g_y2[BATCH * MID * HW];   // relu(bn2(conv2(y1))) * m

// ---------------------------------------------------------------------------
// Kernel 1: 1x1 grouped conv (512->128) + BN + ReLU (+mask), 8x8 tile.
// CTA = (tile, group-pair, batch), 256 thr. Thread = 4px x 4oc.
// ic chunks of 32, SINGLE x buffer + 4x float4 register prefetch:
// 8 syncs total, 512 FFMA between barriers.
// ---------------------------------------------------------------------------
__global__ __launch_bounds__(256) void k1_conv1(
    const float* __restrict__ x, const float* __restrict__ mask,
    const float* __restrict__ w1,
    const float* __restrict__ g1, const float* __restrict__ b1,
    const float* __restrict__ m1, const float* __restrict__ v1)
{
    const int bh = blockIdx.x / 7, bw = blockIdx.x % 7;
    const int gp = blockIdx.y, b = blockIdx.z;      // gp: group pair (0/1)
    const int h0 = bh * 8, w0 = bw * 8;
    const int t = threadIdx.x;
    const int ocq = t >> 4;            // [0,16): 4-oc slice within 64 oc
    const int pxq = t & 15;            // [0,16): 4-px quad
    const int r = pxq >> 1, cst = (pxq & 1) * 4;

    const float m0 = mask[((b * GRP + gp * 2 + 0) * MH + bh) * MW + bw];
    const float m1v = mask[((b * GRP + gp * 2 + 1) * MH + bh) * MW + bw];

    if (m0 == 0.0f && m1v == 0.0f) {
        const float4 z = make_float4(0.f, 0.f, 0.f, 0.f);
        #pragma unroll
        for (int k = 0; k < 4; k++) {
            int gc = gp * 64 + ocq * 4 + k;
            *(float4*)&g_y1[((b * MID + gc) * H + h0 + r) * W + w0 + cst] = z;
        }
        return;
    }

    __shared__ float  w_s[128][68];     // [ic][oc 0..63], pad 68 (34.8 KB)
    __shared__ float4 x_s[2][32][16];   // [grp][ic-in-chunk][pxq] (8 KB)

    // weights for both groups: w1[(gp*64+oc)*128 + ic] -> w_s[ic][oc]
    const float* w1g = w1 + (gp * 64) * 128;
    #pragma unroll
    for (int i = t; i < 64 * 128; i += 256)
        w_s[i & 127][i >> 7] = w1g[i];

    // loader: 4 float4 per thread per 32-ic chunk; id = t + j*256
    //   grp = id>>9, ic = (id>>4)&31, p4 = id&15
    const int myg = ocq >> 3;               // this thread's group (warp-uniform)
    const bool active = (myg ? m1v : m0) != 0.0f;

    float4 pre[4];
    const float* xptr[4];
    bool  lact[4];
    int   sic[4], sp4v[4], sgg[4];
    #pragma unroll
    for (int j = 0; j < 4; j++) {
        int id = t + j * 256;
        int gg = id >> 9, ic = (id >> 4) & 31, p4 = id & 15;
        int rr = p4 >> 1, c2 = (p4 & 1) * 4;
        sgg[j] = gg; sic[j] = ic; sp4v[j] = p4;
        lact[j] = (gg ? m1v : m0) != 0.0f;
        xptr[j] = x + ((long)(b * CIN + (gp * 2 + gg) * 128 + ic) * H + h0 + rr) * W + w0 + c2;
    }

    // prologue: load chunk 0 into smem
    #pragma unroll
    for (int j = 0; j < 4; j++) {
        float4 v = make_float4(0.f, 0.f, 0.f, 0.f);
        if (lact[j]) v = *(const float4*)xptr[j];
        x_s[sgg[j]][sic[j]][sp4v[j]] = v;
    }
    __syncthreads();

    float acc[4][4];
    #pragma unroll
    for (int k = 0; k < 4; k++)
        #pragma unroll
        for (int q = 0; q < 4; q++) acc[k][q] = 0.0f;

    for (int cc = 0; cc < 4; cc++) {        // 4 chunks of 32 ic
        // prefetch next chunk into registers
        if (cc < 3) {
            #pragma unroll
            for (int j = 0; j < 4; j++) {
                pre[j] = make_float4(0.f, 0.f, 0.f, 0.f);
                if (lact[j]) pre[j] = *(const float4*)(xptr[j] + (long)(cc + 1) * 32 * HW);
            }
        }
        if (active) {
            #pragma unroll
            for (int icc = 0; icc < 32; icc++) {
                float4 xv = x_s[myg][icc][pxq];
                float4 wv = *(const float4*)&w_s[cc * 32 + icc][ocq * 4];
                acc[0][0] += wv.x * xv.x; acc[0][1] += wv.x * xv.y;
                acc[0][2] += wv.x * xv.z; acc[0][3] += wv.x * xv.w;
                acc[1][0] += wv.y * xv.x; acc[1][1] += wv.y * xv.y;
                acc[1][2] += wv.y * xv.z; acc[1][3] += wv.y * xv.w;
                acc[2][0] += wv.z * xv.x; acc[2][1] += wv.z * xv.y;
                acc[2][2] += wv.z * xv.z; acc[2][3] += wv.z * xv.w;
                acc[3][0] += wv.w * xv.x; acc[3][1] += wv.w * xv.y;
                acc[3][2] += wv.w * xv.z; acc[3][3] += wv.w * xv.w;
            }
        }
        if (cc < 3) {
            __syncthreads();                 // everyone done reading x_s
            #pragma unroll
            for (int j = 0; j < 4; j++)
                x_s[sgg[j]][sic[j]][sp4v[j]] = pre[j];
            __syncthreads();                 // chunk visible
        }
    }

    const float mymask = myg ? m1v : m0;
    #pragma unroll
    for (int k = 0; k < 4; k++) {
        int gc = gp * 64 + ocq * 4 + k;
        float sc = g1[gc] * rsqrtf(v1[gc] + EPSV);
        float bi = b1[gc] - m1[gc] * sc;
        float4 v;
        if (mymask != 0.0f) {
            v.x = fmaxf(acc[k][0] * sc + bi, 0.0f);
            v.y = fmaxf(acc[k][1] * sc + bi, 0.0f);
            v.z = fmaxf(acc[k][2] * sc + bi, 0.0f);
            v.w = fmaxf(acc[k][3] * sc + bi, 0.0f);
        } else {
            v = make_float4(0.f, 0.f, 0.f, 0.f);
        }
        *(float4*)&g_y1[((b * MID + gc) * H + h0 + r) * W + w0 + cst] = v;
    }
}

// ---------------------------------------------------------------------------
// Kernel 2: 3x3 grouped conv (128->128, pad 1) + BN + ReLU + mask.
// CTA = (tile, group, batch), 128 thr, thread = 4px x 4oc.
// Weight slab split into two 16-ic phases -> smem 33.5 KB (6 CTA/SM).
// Per ic: 18 scalar LDS + 9 LDS.128 + 144 FFMA (FFMA-pipe bound).
// ---------------------------------------------------------------------------
#define K2_HALO   3200                     // 32 * 100 floats
#define K2_WSLAB  (16 * 9 * 36)            // [icc][tap][oc pad36] per phase
#define K2_SMEM   ((K2_HALO + K2_WSLAB) * 4)

__global__ __launch_bounds__(128) void k2_conv2(
    const float* __restrict__ mask,
    const float* __restrict__ w2,
    const float* __restrict__ g2, const float* __restrict__ b2,
    const float* __restrict__ m2, const float* __restrict__ v2)
{
    const int bh = blockIdx.x / 7, bw = blockIdx.x % 7;
    const int g = blockIdx.y, b = blockIdx.z;
    const int h0 = bh * 8, w0 = bw * 8;
    const int t = threadIdx.x;
    const int pxq = t >> 3;                // [0,16)
    const int ocq = t & 7;                 // [0,8): 4-oc slice
    const int r = pxq >> 1, cst = (pxq & 1) * 4;

    const float m = mask[((b * GRP + g) * MH + bh) * MW + bw];

    if (m == 0.0f) {
        const float4 z = make_float4(0.f, 0.f, 0.f, 0.f);
        #pragma unroll
        for (int k = 0; k < 4; k++) {
            int gc = g * 32 + ocq * 4 + k;
            *(float4*)&g_y2[((b * MID + gc) * H + h0 + r) * W + w0 + cst] = z;
        }
        return;
    }

    extern __shared__ float sm[];
    float* in_s = sm;                      // [32][100]
    float* w_s  = sm + K2_HALO;            // [icc][tap][oc]: icc*324 + tap*36 + oc

    // halo (y1 already post-mask; zero-pad borders)
    for (int i = t; i < 32 * 100; i += 128) {
        int ic = i / 100, p = i % 100;
        int rr = h0 + p / 10 - 1, c2 = w0 + p % 10 - 1;
        float v = 0.0f;
        if (rr >= 0 && rr < H && c2 >= 0 && c2 < W)
            v = g_y1[((b * MID + g * 32 + ic) * H + rr) * W + c2];
        in_s[ic * 100 + p] = v;
    }

    float acc[4][4];
    #pragma unroll
    for (int k = 0; k < 4; k++)
        #pragma unroll
        for (int q = 0; q < 4; q++) acc[k][q] = 0.0f;

    const float* w2g = w2 + (g * 32) * 288;   // [oc=32][ic=32][9]

    for (int ch = 0; ch < 2; ch++) {          // two 16-ic weight phases
        if (ch) __syncthreads();              // done reading previous w_s
        // weights: w_s[icc][kk][oc] for ic in [ch*16, ch*16+16)
        for (int i = t; i < 32 * 16 * 9; i += 128) {
            int oc = i / 144, rem = i % 144;
            int icc = rem / 9, kk = rem % 9;
            w_s[icc * 324 + kk * 36 + oc] = w2g[oc * 288 + (ch * 16 + icc) * 9 + kk];
        }
        __syncthreads();

        #pragma unroll 4
        for (int icc = 0; icc < 16; icc++) {
            int ic = ch * 16 + icc;
            float xr[3][6];
            #pragma unroll
            for (int kr = 0; kr < 3; kr++)
                #pragma unroll
                for (int j = 0; j < 6; j++)
                    xr[kr][j] = in_s[ic * 100 + (r + kr) * 10 + cst + j];
            #pragma unroll
            for (int kr = 0; kr < 3; kr++) {
                #pragma unroll
                for (int kc = 0; kc < 3; kc++) {
                    float4 wv = *(const float4*)&w_s[icc * 324 + (kr * 3 + kc) * 36 + ocq * 4];
                    #pragma unroll
                    for (int q = 0; q < 4; q++) {
                        float xv = xr[kr][q + kc];
                        acc[0][q] += wv.x * xv;
                        acc[1][q] += wv.y * xv;
                        acc[2][q] += wv.z * xv;
                        acc[3][q] += wv.w * xv;
                    }
                }
            }
        }
    }

    #pragma unroll
    for (int k = 0; k < 4; k++) {
        int gc = g * 32 + ocq * 4 + k;
        float sc = g2[gc] * rsqrtf(v2[gc] + EPSV);
        float bi = b2[gc] - m2[gc] * sc;
        float4 v;
        v.x = fmaxf(acc[k][0] * sc + bi, 0.0f);
        v.y = fmaxf(acc[k][1] * sc + bi, 0.0f);
        v.z = fmaxf(acc[k][2] * sc + bi, 0.0f);
        v.w = fmaxf(acc[k][3] * sc + bi, 0.0f);
        *(float4*)&g_y2[((b * MID + gc) * H + h0 + r) * W + w0 + cst] = v;
    }
}

// ---------------------------------------------------------------------------
// Kernel 3: 1x1 grouped conv (128->512) + BN + residual + ReLU.
// Thread: 4 px x 8 oc. Per ic: LDS.128(x) + 2x LDS.128(w) + 32 FFMA.
// mask==0 -> out = relu(bias3 + x).
// ---------------------------------------------------------------------------
__global__ __launch_bounds__(256) void k3_conv3(
    const float* __restrict__ x, const float* __restrict__ mask,
    const float* __restrict__ w3,
    const float* __restrict__ g3, const float* __restrict__ b3,
    const float* __restrict__ m3, const float* __restrict__ v3,
    float* __restrict__ out)
{
    const int bh = blockIdx.x / 7, bw = blockIdx.x % 7;
    const int g = blockIdx.y, b = blockIdx.z;
    const int h0 = bh * 8, w0 = bw * 8;
    const int t = threadIdx.x;
    const int pxq = t >> 4, ocp = t & 15;
    const int r = pxq >> 1, cst = (pxq & 1) * 4;

    const float m = mask[((b * GRP + g) * MH + bh) * MW + bw];

    if (m == 0.0f) {
        #pragma unroll
        for (int k = 0; k < 8; k++) {
            int gc = g * 128 + ocp * 8 + k;
            float sc = g3[gc] * rsqrtf(v3[gc] + EPSV);
            float bi = b3[gc] - m3[gc] * sc;
            long idx = ((long)(b * CIN + gc) * H + h0 + r) * W + w0 + cst;
            float4 xv = *(const float4*)&x[idx];
            float4 v;
            v.x = fmaxf(bi + xv.x, 0.0f);
            v.y = fmaxf(bi + xv.y, 0.0f);
            v.z = fmaxf(bi + xv.z, 0.0f);
            v.w = fmaxf(bi + xv.w, 0.0f);
            *(float4*)&out[idx] = v;
        }
        return;
    }

    __shared__ float  w_s[32][132];     // [ic][oc], padded
    __shared__ float4 y_s[32][16];      // [ic][pxq]

    const float* w3g = w3 + (g * 128) * 32;     // [oc=128][ic=32]
    #pragma unroll
    for (int i = t; i < 128 * 32; i += 256)
        w_s[i & 31][i >> 5] = w3g[i];
    #pragma unroll
    for (int j = 0; j < 2; j++) {
        int i = t + j * 256;
        int ic = i >> 4, p4 = i & 15;
        int rr = p4 >> 1, c2 = (p4 & 1) * 4;
        y_s[ic][p4] = *(const float4*)&g_y2[
            ((b * MID + g * 32 + ic) * H + h0 + rr) * W + w0 + c2];
    }
    __syncthreads();

    float acc[8][4];
    #pragma unroll
    for (int k = 0; k < 8; k++)
        #pragma unroll
        for (int q = 0; q < 4; q++) acc[k][q] = 0.0f;

    #pragma unroll 4
    for (int ic = 0; ic < 32; ic++) {
        float4 xv = y_s[ic][pxq];
        const float* wr = &w_s[ic][ocp * 8];
        float4 wa = *(const float4*)wr;
        float4 wb = *(const float4*)(wr + 4);
        float wk[8] = {wa.x, wa.y, wa.z, wa.w, wb.x, wb.y, wb.z, wb.w};
        #pragma unroll
        for (int k = 0; k < 8; k++) {
            acc[k][0] += wk[k] * xv.x;
            acc[k][1] += wk[k] * xv.y;
            acc[k][2] += wk[k] * xv.z;
            acc[k][3] += wk[k] * xv.w;
        }
    }

    #pragma unroll
    for (int k = 0; k < 8; k++) {
        int gc = g * 128 + ocp * 8 + k;
        float sc = g3[gc] * rsqrtf(v3[gc] + EPSV);
        float bi = b3[gc] - m3[gc] * sc;
        long idx = ((long)(b * CIN + gc) * H + h0 + r) * W + w0 + cst;
        float4 xv = *(const float4*)&x[idx];
        float4 v;
        v.x = fmaxf(acc[k][0] * sc + bi + xv.x, 0.0f);
        v.y = fmaxf(acc[k][1] * sc + bi + xv.y, 0.0f);
        v.z = fmaxf(acc[k][2] * sc + bi + xv.z, 0.0f);
        v.w = fmaxf(acc[k][3] * sc + bi + xv.w, 0.0f);
        *(float4*)&out[idx] = v;
    }
}

// ---------------------------------------------------------------------------
extern "C" void kernel_launch(void* const* d_in, const int* in_sizes, int n_in,
                              void* d_out, int out_size)
{
    const float* x    = (const float*)d_in[0];
    const float* mask = (const float*)d_in[1];
    const float* w1   = (const float*)d_in[2];
    const float* g1   = (const float*)d_in[3];
    const float* b1   = (const float*)d_in[4];
    const float* m1   = (const float*)d_in[5];
    const float* v1   = (const float*)d_in[6];
    const float* w2   = (const float*)d_in[7];
    const float* g2   = (const float*)d_in[8];
    const float* b2   = (const float*)d_in[9];
    const float* m2   = (const float*)d_in[10];
    const float* v2   = (const float*)d_in[11];
    const float* w3   = (const float*)d_in[12];
    const float* g3   = (const float*)d_in[13];
    const float* b3   = (const float*)d_in[14];
    const float* m3   = (const float*)d_in[15];
    const float* v3   = (const float*)d_in[16];
    float* out = (float*)d_out;

    cudaFuncSetAttribute(k2_conv2, cudaFuncAttributeMaxDynamicSharedMemorySize, K2_SMEM);

    dim3 grid1(49, 2, BATCH);
    k1_conv1<<<grid1, 256>>>(x, mask, w1, g1, b1, m1, v1);
    dim3 grid2(49, GRP, BATCH);
    k2_conv2<<<grid2, 128, K2_SMEM>>>(mask, w2, g2, b2, m2, v2);
    k3_conv3<<<grid2, 256>>>(x, mask, w3, g3, b3, m3, v3, out);
}